// round 12
// baseline (speedup 1.0000x reference)
#include <cuda_runtime.h>
#include <cuda_fp16.h>
#include <cstdint>

#define SEQ 2048
#define DMODEL 1024
#define NH 16
#define DK 64
#define NB 2
#define ROWS (NB*SEQ)

// 0.125 * log2(e): folds the 1/sqrt(dk) scale and the exp->exp2 change
#define QSCALE 0.18033688f

// ---------------- scratch (device globals: allocation-free) ----------------
__device__ __half h_query[ROWS*DMODEL];
__device__ __half h_key  [ROWS*DMODEL];
__device__ __half h_value[ROWS*DMODEL];
__device__ __half h_Wq[DMODEL*DMODEL];
__device__ __half h_Wo[DMODEL*DMODEL];
__device__ __half h_Wk[DMODEL*DK];
__device__ __half h_Wv[DMODEL*DK];
__device__ __half h_q [ROWS*DMODEL];
__device__ __half h_kv[ROWS*2*DK];        // packed [4096][128]: cols 0-63 K, 64-127 V
__device__ __half h_x [ROWS*DMODEL];

// ---------------- ptx helpers ----------------
__device__ __forceinline__ unsigned su32(const void* p){
    return (unsigned)__cvta_generic_to_shared(p);
}
__device__ __forceinline__ void cp16(unsigned s, const void* g){
    asm volatile("cp.async.ca.shared.global [%0], [%1], 16;" :: "r"(s), "l"(g));
}
__device__ __forceinline__ void cp_commit(){ asm volatile("cp.async.commit_group;"); }
template<int N> __device__ __forceinline__ void cp_wait(){
    asm volatile("cp.async.wait_group %0;" :: "n"(N));
}
__device__ __forceinline__ void ldm4(unsigned& r0,unsigned& r1,unsigned& r2,unsigned& r3,unsigned a){
    asm volatile("ldmatrix.sync.aligned.m8n8.x4.shared.b16 {%0,%1,%2,%3}, [%4];"
        : "=r"(r0),"=r"(r1),"=r"(r2),"=r"(r3) : "r"(a));
}
__device__ __forceinline__ void ldm4t(unsigned& r0,unsigned& r1,unsigned& r2,unsigned& r3,unsigned a){
    asm volatile("ldmatrix.sync.aligned.m8n8.x4.trans.shared.b16 {%0,%1,%2,%3}, [%4];"
        : "=r"(r0),"=r"(r1),"=r"(r2),"=r"(r3) : "r"(a));
}
__device__ __forceinline__ void ldm2t(unsigned& r0,unsigned& r1,unsigned a){
    asm volatile("ldmatrix.sync.aligned.m8n8.x2.trans.shared.b16 {%0,%1}, [%2];"
        : "=r"(r0),"=r"(r1) : "r"(a));
}
__device__ __forceinline__ void mma_f16(float* c, unsigned a0,unsigned a1,unsigned a2,unsigned a3,
                                        unsigned b0, unsigned b1){
    asm volatile("mma.sync.aligned.m16n8k16.row.col.f32.f16.f16.f32 "
        "{%0,%1,%2,%3},{%4,%5,%6,%7},{%8,%9},{%0,%1,%2,%3};"
        : "+f"(c[0]),"+f"(c[1]),"+f"(c[2]),"+f"(c[3])
        : "r"(a0),"r"(a1),"r"(a2),"r"(a3),"r"(b0),"r"(b1));
}
__device__ __forceinline__ float ex2(float x){
    float r; asm("ex2.approx.f32 %0, %1;" : "=f"(r) : "f"(x)); return r;
}
__device__ __forceinline__ void st2(__half* p, float x, float y){
    *(__half2*)p = __floats2half2_rn(x, y);
}
__device__ __forceinline__ void st2(float* p, float x, float y){
    *(float2*)p = make_float2(x, y);
}

// ---------------- fp32 -> fp16 converts (merged launches, 8 elem/thread) ----
__global__ void f2h_acts(const float* __restrict__ q, const float* __restrict__ k,
                         const float* __restrict__ v){
    const float* s; __half* d;
    if      (blockIdx.z == 0){ s = q; d = h_query; }
    else if (blockIdx.z == 1){ s = k; d = h_key;   }
    else                     { s = v; d = h_value; }
    int i = (blockIdx.x*blockDim.x + threadIdx.x)*8;
    float4 a = *(const float4*)&s[i];
    float4 b2 = *(const float4*)&s[i+4];
    *(__half2*)&d[i]   = __floats2half2_rn(a.x, a.y);
    *(__half2*)&d[i+2] = __floats2half2_rn(a.z, a.w);
    *(__half2*)&d[i+4] = __floats2half2_rn(b2.x, b2.y);
    *(__half2*)&d[i+6] = __floats2half2_rn(b2.z, b2.w);
}
__global__ void f2h_wts(const float* __restrict__ Wq, const float* __restrict__ Wo,
                        const float* __restrict__ Wk, const float* __restrict__ Wv){
    const float* s; __half* d; int n; float sc;
    if      (blockIdx.z == 0){ s=Wq; d=h_Wq; n=DMODEL*DMODEL; sc=QSCALE; }
    else if (blockIdx.z == 1){ s=Wo; d=h_Wo; n=DMODEL*DMODEL; sc=1.f; }
    else if (blockIdx.z == 2){ s=Wk; d=h_Wk; n=DMODEL*DK;     sc=1.f; }
    else                     { s=Wv; d=h_Wv; n=DMODEL*DK;     sc=1.f; }
    int i = (blockIdx.x*blockDim.x + threadIdx.x)*8;
    if (i < n){
        float4 a = *(const float4*)&s[i];
        float4 b2 = *(const float4*)&s[i+4];
        *(__half2*)&d[i]   = __floats2half2_rn(a.x*sc, a.y*sc);
        *(__half2*)&d[i+2] = __floats2half2_rn(a.z*sc, a.w*sc);
        *(__half2*)&d[i+4] = __floats2half2_rn(b2.x*sc, b2.y*sc);
        *(__half2*)&d[i+6] = __floats2half2_rn(b2.z*sc, b2.w*sc);
    }
}

// ---------------------------------------------------------------------------
// fp16 GEMM core (unchanged from R11)
// ---------------------------------------------------------------------------
template<int BM, int BN, int STAGES, typename OUT>
__device__ __forceinline__ void gemm_core(
    const __half* __restrict__ A, const __half* __restrict__ W,
    const float* __restrict__ bias, OUT* __restrict__ C,
    int M, int N, int K, float bscale, int CST, int coff)
{
    constexpr int AST = 40;
    constexpr int WST = BN + 8;
    constexpr int ASZ = BM*AST;
    constexpr int WSZ = 32*WST;
    constexpr int MW  = BM/32;
    constexpr int NW  = 8/MW;
    constexpr int WN  = BN/NW;
    constexpr int NG  = WN/16;

    extern __shared__ __half gsm[];
    __half* sAbase = gsm;
    __half* sWbase = gsm + STAGES*ASZ;

    const int tid = threadIdx.x, warp = tid>>5, lane = tid&31;
    const int wm = warp % MW, wn = warp / MW;
    const int m0 = blockIdx.y*BM, n0 = blockIdx.x*BN;
    const int g = lane>>2, t = lane&3;

    float acc[2][NG*2][4];
#pragma unroll
    for (int a=0;a<2;a++)
#pragma unroll
        for (int b=0;b<NG*2;b++)
#pragma unroll
            for (int c=0;c<4;c++) acc[a][b][c]=0.f;

    auto stage = [&](int kt, int buf){
        __half* sA = sAbase + buf*ASZ;
        __half* sW = sWbase + buf*WSZ;
#pragma unroll
        for (int c = tid; c < BM*4; c += 256){
            int r = c>>2, cc = c&3;
            cp16(su32(&sA[r*AST + cc*8]),
                 &A[(size_t)(m0+r)*K + kt*32 + cc*8]);
        }
        constexpr int WC = BN/8;
#pragma unroll
        for (int c2=tid; c2 < 32*WC; c2 += 256){
            int r = c2/WC, cc = c2%WC;
            cp16(su32(&sW[r*WST + cc*8]),
                 &W[(size_t)(kt*32+r)*N + n0 + cc*8]);
        }
    };

    const int KT = K/32;
#pragma unroll
    for (int p=0; p<STAGES-1; p++){ stage(p, p); cp_commit(); }

    for (int kt = 0; kt < KT; kt++){
        if (kt+STAGES-1 < KT) stage(kt+STAGES-1, (kt+STAGES-1)%STAGES);
        cp_commit();
        cp_wait<STAGES-1>();
        __syncthreads();
        const __half* cA = sAbase + (kt%STAGES)*ASZ;
        const __half* cW = sWbase + (kt%STAGES)*WSZ;
#pragma unroll
        for (int ks=0; ks<2; ks++){
            unsigned a[2][4];
#pragma unroll
            for (int mt=0; mt<2; mt++){
                int row = wm*32 + mt*16 + (lane&7) + ((lane>>3)&1)*8;
                int col = ks*16 + (lane>>4)*8;
                ldm4(a[mt][0],a[mt][1],a[mt][2],a[mt][3], su32(&cA[row*AST+col]));
            }
            unsigned bfr[NG][4];
#pragma unroll
            for (int ng=0; ng<NG; ng++){
                int row = ks*16 + (lane&15);
                int col = wn*WN + ng*16 + (lane>>4)*8;
                ldm4t(bfr[ng][0],bfr[ng][1],bfr[ng][2],bfr[ng][3], su32(&cW[row*WST+col]));
            }
#pragma unroll
            for (int mt=0; mt<2; mt++)
#pragma unroll
                for (int ng=0; ng<NG; ng++){
                    mma_f16(acc[mt][ng*2],   a[mt][0],a[mt][1],a[mt][2],a[mt][3],
                            bfr[ng][0],bfr[ng][1]);
                    mma_f16(acc[mt][ng*2+1], a[mt][0],a[mt][1],a[mt][2],a[mt][3],
                            bfr[ng][2],bfr[ng][3]);
                }
        }
        __syncthreads();
    }

#pragma unroll
    for (int mt=0; mt<2; mt++){
        int row = m0 + wm*32 + mt*16;
#pragma unroll
        for (int nt=0; nt<NG*2; nt++){
            int col = n0 + wn*WN + nt*8 + 2*t;
            float b0 = bias[col]*bscale, b1 = bias[col+1]*bscale;
            st2(&C[(size_t)(row+g  )*CST + coff + col], acc[mt][nt][0]+b0, acc[mt][nt][1]+b1);
            st2(&C[(size_t)(row+g+8)*CST + coff + col], acc[mt][nt][2]+b0, acc[mt][nt][3]+b1);
        }
    }
}

template<typename OUT>
__global__ __launch_bounds__(256,2) void gemm128_k(
    const __half* __restrict__ A, const __half* __restrict__ W,
    const float* __restrict__ bias, OUT* __restrict__ C,
    int M, int N, int K, float bscale)
{
    gemm_core<128,128,3,OUT>(A, W, bias, C, M, N, K, bscale, N, 0);
}

__global__ __launch_bounds__(256,2) void gemm_kv_k(
    const __half* __restrict__ Ak, const __half* __restrict__ Av,
    const __half* __restrict__ Wk, const __half* __restrict__ Wv,
    const float* __restrict__ bk, const float* __restrict__ bv,
    __half* __restrict__ C)
{
    const int z = blockIdx.z;
    gemm_core<64,64,4,__half>(z ? Av : Ak, z ? Wv : Wk, z ? bv : bk, C,
                              ROWS, DK, DMODEL, 1.f, 2*DK, z*DK);
}

#define GSM128 ((3*(128*40) + 3*(32*136))*2)    // 56832
#define GSMKV  ((4*(64*40)  + 4*(32*72))*2)     // 38912

// ---------------------------------------------------------------------------
// fp16 flash attention, MQA flattened. CTA = 128 rows = 8 s x 16 heads,
// 128 threads / 4 warps; EACH WARP OWNS 2 s-VALUES (two m16 tiles) so every
// K/V fragment load feeds 2x the mma work (halves the LDSM floor per HMMA).
// launch_bounds(128,2): 256-reg budget, 2 CTAs/SM.
// Q pre-scaled by 0.125*log2(e) -> softmax via exp2 (f16x2 MUFU), online max,
// mask bias as mma C-init (exact), warp-voted rescale skip (exact),
// denominator l via ones-column mma. 2-stage static-smem cp.async pipeline.
// ---------------------------------------------------------------------------
__global__ __launch_bounds__(128,2) void flash_h(
    const __half* __restrict__ qp, const __half* __restrict__ kvp,
    const int* __restrict__ mask, __half* __restrict__ xo)
{
    constexpr int ST = 72;    // smem row stride halfs; cols 64-71 = [1,0,...,0]
    __shared__ __half sK[2][64*ST];
    __shared__ __half sV[2][64*ST];
    __shared__ int    sM[2][8*64];
    __half* sQ = &sK[0][0];   // 128*72 halfs == both sK buffers, prologue only

    const int tid = threadIdx.x, warp = tid>>5, lane = tid&31;
    const int g = lane>>2, t = lane&3;
    const int m0 = blockIdx.x*128;
    const int b  = m0 >> 15;
    const int s0 = (m0 & 32767) >> 4;
    const int sbase = b*SEQ;

    // ---- stage Q [128][64]: thread tid stages row tid (8 chunks) ----
    {
#pragma unroll
        for (int i=0;i<8;i++){
            cp16(su32(&sQ[tid*ST + i*8]),
                 &qp[(size_t)(sbase + s0 + (tid>>4))*DMODEL + (tid&15)*64 + i*8]);
        }
        cp_commit(); cp_wait<0>();
        __syncthreads();
    }
    // Q fragments for both tiles (tt = s_local parity): rows (warp*2+tt)*16..+15
    unsigned qa[2][4][4];
#pragma unroll
    for (int tt=0; tt<2; tt++)
#pragma unroll
        for (int ks=0; ks<4; ks++){
            int row = (warp*2+tt)*16 + (lane&7) + ((lane>>3)&1)*8;
            int col = ks*16 + (lane>>4)*8;
            ldm4(qa[tt][ks][0],qa[tt][ks][1],qa[tt][ks][2],qa[tt][ks][3],
                 su32(&sQ[row*ST+col]));
        }
    __syncthreads();    // sQ region free -> K buffers

    // ---- init V ones-column region (cols 64-71) for both buffers ----
    {
        int buf = tid >> 6, row = tid & 63;
        __half tmp[8] = {__float2half(1.f),__half(0),__half(0),__half(0),
                         __half(0),__half(0),__half(0),__half(0)};
        *(uint4*)&sV[buf][row*ST + 64] = *(uint4*)&tmp[0];
    }

    float o[2][8][4];
#pragma unroll
    for (int tt=0;tt<2;tt++)
#pragma unroll
        for (int i=0;i<8;i++){ o[tt][i][0]=0.f;o[tt][i][1]=0.f;o[tt][i][2]=0.f;o[tt][i][3]=0.f; }
    float lacc[2][4] = {{0.f,0.f,0.f,0.f},{0.f,0.f,0.f,0.f}};
    float mrow[2][2] = {{-1e30f,-1e30f},{-1e30f,-1e30f}};

    auto stage = [&](int nk, int buf){
        int c = tid*4;
#pragma unroll
        for (int i=0;i<4;i++,c++){
            int r = c>>3, cc = c&7;
            const __half* kvrow = &kvp[(size_t)(sbase + nk + r)*(2*DK)];
            cp16(su32(&sK[buf][r*ST + cc*8]), kvrow + cc*8);
            cp16(su32(&sV[buf][r*ST + cc*8]), kvrow + DK + cc*8);
        }
        {
            int r = tid>>4, cc = tid&15;
            cp16(su32(&sM[buf][r*64 + cc*4]),
                 &mask[((size_t)b*SEQ + s0 + r)*SEQ + nk + cc*4]);
        }
    };

    stage(0,0); cp_commit();

    for (int it = 0; it < SEQ/64; it++){
        if (it+1 < SEQ/64){ stage((it+1)*64, (it+1)&1); cp_commit(); cp_wait<1>(); }
        else              { cp_wait<0>(); }
        __syncthreads();
        const __half* cK = sK[it&1];
        const __half* cV = sV[it&1];
        const int*    cM = sM[it&1];

        // ---- S = Q K^T with mask bias as C-init (log2 domain), both tiles ----
        float sf[2][8][4];
#pragma unroll
        for (int jt=0; jt<8; jt++){
            unsigned kb[8];
            {
                int row = jt*8 + (lane&7);
                int col = (lane>>3)*8;
                ldm4(kb[0],kb[1],kb[2],kb[3], su32(&cK[row*ST + col]));
                ldm4(kb[4],kb[5],kb[6],kb[7], su32(&cK[row*ST + 32 + col]));
            }
#pragma unroll
            for (int tt=0; tt<2; tt++){
                float mb0 = cM[(warp*2+tt)*64 + jt*8 + 2*t    ] ? 0.f : -1e9f;
                float mb1 = cM[(warp*2+tt)*64 + jt*8 + 2*t + 1] ? 0.f : -1e9f;
                float* s = sf[tt][jt];
                s[0]=mb0; s[1]=mb1; s[2]=mb0; s[3]=mb1;
                mma_f16(s, qa[tt][0][0],qa[tt][0][1],qa[tt][0][2],qa[tt][0][3], kb[0],kb[1]);
                mma_f16(s, qa[tt][1][0],qa[tt][1][1],qa[tt][1][2],qa[tt][1][3], kb[2],kb[3]);
                mma_f16(s, qa[tt][2][0],qa[tt][2][1],qa[tt][2][2],qa[tt][2][3], kb[4],kb[5]);
                mma_f16(s, qa[tt][3][0],qa[tt][3][1],qa[tt][3][2],qa[tt][3][3], kb[6],kb[7]);
            }
        }

        // ---- online softmax (base 2) per tile ----
        float mn[2][2];
        bool unchanged = true;
#pragma unroll
        for (int tt=0; tt<2; tt++){
            float mx0=-1e30f, mx1=-1e30f;
#pragma unroll
            for (int jt=0; jt<8; jt++){
                mx0 = fmaxf(mx0, fmaxf(sf[tt][jt][0], sf[tt][jt][1]));
                mx1 = fmaxf(mx1, fmaxf(sf[tt][jt][2], sf[tt][jt][3]));
            }
            mx0 = fmaxf(mx0, __shfl_xor_sync(0xffffffffu, mx0, 1));
            mx0 = fmaxf(mx0, __shfl_xor_sync(0xffffffffu, mx0, 2));
            mx1 = fmaxf(mx1, __shfl_xor_sync(0xffffffffu, mx1, 1));
            mx1 = fmaxf(mx1, __shfl_xor_sync(0xffffffffu, mx1, 2));
            mn[tt][0] = fmaxf(mrow[tt][0], mx0);
            mn[tt][1] = fmaxf(mrow[tt][1], mx1);
            unchanged = unchanged && (mn[tt][0] == mrow[tt][0]) && (mn[tt][1] == mrow[tt][1]);
        }
        // rescale only when some row max increased (skip is exact: sc==1.0)
        if (!__all_sync(0xffffffffu, unchanged)){
#pragma unroll
            for (int tt=0; tt<2; tt++){
                float sc0 = ex2(mrow[tt][0] - mn[tt][0]);
                float sc1 = ex2(mrow[tt][1] - mn[tt][1]);
#pragma unroll
                for (int nv=0; nv<8; nv++){
                    o[tt][nv][0]*=sc0; o[tt][nv][1]*=sc0;
                    o[tt][nv][2]*=sc1; o[tt][nv][3]*=sc1;
                }
                lacc[tt][0]*=sc0; lacc[tt][1]*=sc0; lacc[tt][2]*=sc1; lacc[tt][3]*=sc1;
            }
        }
#pragma unroll
        for (int tt=0; tt<2; tt++){ mrow[tt][0]=mn[tt][0]; mrow[tt][1]=mn[tt][1]; }

        unsigned pl[2][8], ph[2][8];
#pragma unroll
        for (int tt=0; tt<2; tt++)
#pragma unroll
            for (int jt=0; jt<8; jt++){
                __half2 e0 = h2exp2(__floats2half2_rn(sf[tt][jt][0]-mn[tt][0], sf[tt][jt][1]-mn[tt][0]));
                __half2 e1 = h2exp2(__floats2half2_rn(sf[tt][jt][2]-mn[tt][1], sf[tt][jt][3]-mn[tt][1]));
                pl[tt][jt] = *(unsigned*)&e0;
                ph[tt][jt] = *(unsigned*)&e1;
            }

        // ---- O += P V ; l += P 1 (shared V fragments feed both tiles) ----
#pragma unroll
        for (int kt2=0; kt2<4; kt2++){
#pragma unroll
            for (int dp=0; dp<4; dp++){
                unsigned r0,r1,r2,r3;
                int row = kt2*16 + (lane&15);
                int col = dp*16 + (lane>>4)*8;
                ldm4t(r0,r1,r2,r3, su32(&cV[row*ST + col]));
#pragma unroll
                for (int tt=0; tt<2; tt++){
                    mma_f16(o[tt][dp*2],   pl[tt][2*kt2],ph[tt][2*kt2],
                            pl[tt][2*kt2+1],ph[tt][2*kt2+1], r0,r1);
                    mma_f16(o[tt][dp*2+1], pl[tt][2*kt2],ph[tt][2*kt2],
                            pl[tt][2*kt2+1],ph[tt][2*kt2+1], r2,r3);
                }
            }
            unsigned l0r,l1r;
            ldm2t(l0r,l1r, su32(&cV[(kt2*16 + (lane&15))*ST + 64]));
#pragma unroll
            for (int tt=0; tt<2; tt++)
                mma_f16(lacc[tt], pl[tt][2*kt2],ph[tt][2*kt2],
                        pl[tt][2*kt2+1],ph[tt][2*kt2+1], l0r,l1r);
        }
        __syncthreads();
    }

    // ---- per tile: broadcast l, normalize, write ----
#pragma unroll
    for (int tt=0; tt<2; tt++){
        float lv0 = __shfl_sync(0xffffffffu, lacc[tt][0], lane & 28);
        float lv1 = __shfl_sync(0xffffffffu, lacc[tt][2], lane & 28);
        float inv0 = 1.f/lv0, inv1 = 1.f/lv1;
        __half* orow = &xo[(size_t)(sbase + s0 + warp*2 + tt)*DMODEL];
#pragma unroll
        for (int nt=0; nt<8; nt++){
            int col = nt*8 + 2*t;
            st2(&orow[g*64 + col],     o[tt][nt][0]*inv0, o[tt][nt][1]*inv0);
            st2(&orow[(g+8)*64 + col], o[tt][nt][2]*inv1, o[tt][nt][3]*inv1);
        }
    }
}

// ---------------------------------------------------------------------------
extern "C" void kernel_launch(void* const* d_in, const int* in_sizes, int n_in,
                              void* d_out, int out_size)
{
    const float* query = (const float*)d_in[0];
    const float* key   = (const float*)d_in[1];
    const float* value = (const float*)d_in[2];
    const int*   mask  = (const int*)  d_in[3];
    const float* Wq = (const float*)d_in[4];
    const float* bq = (const float*)d_in[5];
    const float* Wk = (const float*)d_in[6];
    const float* bk = (const float*)d_in[7];
    const float* Wv = (const float*)d_in[8];
    const float* bv = (const float*)d_in[9];
    const float* Wo = (const float*)d_in[10];
    const float* bo = (const float*)d_in[11];
    float* out = (float*)d_out;

    __half *gquery,*gkey,*gvalue,*gWq,*gWo,*gWk,*gWv,*gq,*gkv,*gx;
    cudaGetSymbolAddress((void**)&gquery, h_query);
    cudaGetSymbolAddress((void**)&gkey,   h_key);
    cudaGetSymbolAddress((void**)&gvalue, h_value);
    cudaGetSymbolAddress((void**)&gWq,    h_Wq);
    cudaGetSymbolAddress((void**)&gWo,    h_Wo);
    cudaGetSymbolAddress((void**)&gWk,    h_Wk);
    cudaGetSymbolAddress((void**)&gWv,    h_Wv);
    cudaGetSymbolAddress((void**)&gq,     h_q);
    cudaGetSymbolAddress((void**)&gkv,    h_kv);
    cudaGetSymbolAddress((void**)&gx,     h_x);

    cudaFuncSetAttribute(gemm128_k<__half>, cudaFuncAttributeMaxDynamicSharedMemorySize, GSM128);
    cudaFuncSetAttribute(gemm128_k<float>,  cudaFuncAttributeMaxDynamicSharedMemorySize, GSM128);
    cudaFuncSetAttribute(gemm_kv_k,         cudaFuncAttributeMaxDynamicSharedMemorySize, GSMKV);

    const int NACT = ROWS*DMODEL;     // 4M
    const int NW   = DMODEL*DMODEL;   // 1M

    // converts: one launch for activations, one for all weights
    f2h_acts<<<dim3(NACT/2048, 1, 3), 256>>>(query, key, value);
    f2h_wts <<<dim3(NW/2048,   1, 4), 256>>>(Wq, Wo, Wk, Wv);

    // projections (Q; K & V merged at BM=64 -> 128 CTAs)
    gemm128_k<__half><<<dim3(DMODEL/128, ROWS/128), 256, GSM128>>>(
        gquery, gWq, bq, gq, ROWS, DMODEL, DMODEL, QSCALE);
    gemm_kv_k<<<dim3(1, ROWS/64, 2), 256, GSMKV>>>(
        gkey, gvalue, gWk, gWv, bk, bv, gkv);

    // fused MQA flash attention (128 threads, 2 s per warp)
    flash_h<<<(NB*SEQ*NH)/128, 128>>>(gq, gkv, mask, gx);

    // output projection (fp32 out)
    gemm128_k<float><<<dim3(DMODEL/128, ROWS/128), 256, GSM128>>>(
        gx, gWo, bo, out, ROWS, DMODEL, DMODEL, 1.f);
}

// round 15
// speedup vs baseline: 1.0520x; 1.0520x over previous
#include <cuda_runtime.h>
#include <cuda_fp16.h>
#include <cstdint>

#define SEQ 2048
#define DMODEL 1024
#define NH 16
#define DK 64
#define NB 2
#define ROWS (NB*SEQ)

// 0.125 * log2(e): folds the 1/sqrt(dk) scale and the exp->exp2 change
#define QSCALE 0.18033688f

// ---------------- scratch (device globals: allocation-free) ----------------
__device__ __half h_query[ROWS*DMODEL];
__device__ __half h_key  [ROWS*DMODEL];
__device__ __half h_value[ROWS*DMODEL];
__device__ __half h_Wq[DMODEL*DMODEL];
__device__ __half h_Wo[DMODEL*DMODEL];
__device__ __half h_Wk[DMODEL*DK];
__device__ __half h_Wv[DMODEL*DK];
__device__ __half h_q [ROWS*DMODEL];
__device__ __half h_kv[ROWS*2*DK];        // packed [4096][128]: cols 0-63 K, 64-127 V
__device__ __half h_x [ROWS*DMODEL];

// ---------------- ptx helpers ----------------
__device__ __forceinline__ unsigned su32(const void* p){
    return (unsigned)__cvta_generic_to_shared(p);
}
__device__ __forceinline__ void cp16(unsigned s, const void* g){
    asm volatile("cp.async.ca.shared.global [%0], [%1], 16;" :: "r"(s), "l"(g));
}
__device__ __forceinline__ void cp_commit(){ asm volatile("cp.async.commit_group;"); }
template<int N> __device__ __forceinline__ void cp_wait(){
    asm volatile("cp.async.wait_group %0;" :: "n"(N));
}
__device__ __forceinline__ void ldm4(unsigned& r0,unsigned& r1,unsigned& r2,unsigned& r3,unsigned a){
    asm volatile("ldmatrix.sync.aligned.m8n8.x4.shared.b16 {%0,%1,%2,%3}, [%4];"
        : "=r"(r0),"=r"(r1),"=r"(r2),"=r"(r3) : "r"(a));
}
__device__ __forceinline__ void ldm4t(unsigned& r0,unsigned& r1,unsigned& r2,unsigned& r3,unsigned a){
    asm volatile("ldmatrix.sync.aligned.m8n8.x4.trans.shared.b16 {%0,%1,%2,%3}, [%4];"
        : "=r"(r0),"=r"(r1),"=r"(r2),"=r"(r3) : "r"(a));
}
__device__ __forceinline__ void ldm2t(unsigned& r0,unsigned& r1,unsigned a){
    asm volatile("ldmatrix.sync.aligned.m8n8.x2.trans.shared.b16 {%0,%1}, [%2];"
        : "=r"(r0),"=r"(r1) : "r"(a));
}
__device__ __forceinline__ void mma_f16(float* c, unsigned a0,unsigned a1,unsigned a2,unsigned a3,
                                        unsigned b0, unsigned b1){
    asm volatile("mma.sync.aligned.m16n8k16.row.col.f32.f16.f16.f32 "
        "{%0,%1,%2,%3},{%4,%5,%6,%7},{%8,%9},{%0,%1,%2,%3};"
        : "+f"(c[0]),"+f"(c[1]),"+f"(c[2]),"+f"(c[3])
        : "r"(a0),"r"(a1),"r"(a2),"r"(a3),"r"(b0),"r"(b1));
}
__device__ __forceinline__ float ex2(float x){
    float r; asm("ex2.approx.f32 %0, %1;" : "=f"(r) : "f"(x)); return r;
}
__device__ __forceinline__ void st2(__half* p, float x, float y){
    *(__half2*)p = __floats2half2_rn(x, y);
}
__device__ __forceinline__ void st2(float* p, float x, float y){
    *(float2*)p = make_float2(x, y);
}

// ---------------- all fp32 -> fp16 converts in ONE launch ----------------
// blocks: [0,2048) query | [2048,4096) key | [4096,6144) value
//         [6144,6656) Wq | [6656,7168) Wo | [7168,7200) Wk | [7200,7232) Wv
__global__ void conv_all(const float* __restrict__ q, const float* __restrict__ k,
                         const float* __restrict__ v, const float* __restrict__ Wq,
                         const float* __restrict__ Wo, const float* __restrict__ Wk,
                         const float* __restrict__ Wv){
    int bid = blockIdx.x;
    const float* s; __half* d; float sc = 1.f; int base;
    if      (bid < 2048){ s=q;  d=h_query; base=bid; }
    else if (bid < 4096){ s=k;  d=h_key;   base=bid-2048; }
    else if (bid < 6144){ s=v;  d=h_value; base=bid-4096; }
    else if (bid < 6656){ s=Wq; d=h_Wq;    base=bid-6144; sc=QSCALE; }
    else if (bid < 7168){ s=Wo; d=h_Wo;    base=bid-6656; }
    else if (bid < 7200){ s=Wk; d=h_Wk;    base=bid-7168; }
    else                { s=Wv; d=h_Wv;    base=bid-7200; }
    int i = (base*256 + threadIdx.x)*8;
    float4 a = *(const float4*)&s[i];
    float4 b2 = *(const float4*)&s[i+4];
    *(__half2*)&d[i]   = __floats2half2_rn(a.x*sc, a.y*sc);
    *(__half2*)&d[i+2] = __floats2half2_rn(a.z*sc, a.w*sc);
    *(__half2*)&d[i+4] = __floats2half2_rn(b2.x*sc, b2.y*sc);
    *(__half2*)&d[i+6] = __floats2half2_rn(b2.z*sc, b2.w*sc);
}

// ---------------------------------------------------------------------------
// fp16 GEMM core: C tile [BM x BN] at (m0, n0) = A[M,K] @ W[K,N] + bias*bscale.
// BK=32, STAGES-deep cp.async pipeline, dynamic smem. 256 threads.
// Output row stride CST (>= N) at column offset coff.
// ---------------------------------------------------------------------------
template<int BM, int BN, int STAGES, typename OUT>
__device__ __forceinline__ void gemm_core(
    const __half* __restrict__ A, const __half* __restrict__ W,
    const float* __restrict__ bias, OUT* __restrict__ C,
    int N, int K, float bscale, int CST, int coff, int m0, int n0)
{
    constexpr int AST = 40;
    constexpr int WST = BN + 8;
    constexpr int ASZ = BM*AST;
    constexpr int WSZ = 32*WST;
    constexpr int MW  = BM/32;
    constexpr int NW  = 8/MW;
    constexpr int WN  = BN/NW;
    constexpr int NG  = WN/16;

    extern __shared__ __half gsm[];
    __half* sAbase = gsm;
    __half* sWbase = gsm + STAGES*ASZ;

    const int tid = threadIdx.x, warp = tid>>5, lane = tid&31;
    const int wm = warp % MW, wn = warp / MW;
    const int g = lane>>2, t = lane&3;

    float acc[2][NG*2][4];
#pragma unroll
    for (int a=0;a<2;a++)
#pragma unroll
        for (int b=0;b<NG*2;b++)
#pragma unroll
            for (int c=0;c<4;c++) acc[a][b][c]=0.f;

    auto stage = [&](int kt, int buf){
        __half* sA = sAbase + buf*ASZ;
        __half* sW = sWbase + buf*WSZ;
#pragma unroll
        for (int c = tid; c < BM*4; c += 256){
            int r = c>>2, cc = c&3;
            cp16(su32(&sA[r*AST + cc*8]),
                 &A[(size_t)(m0+r)*K + kt*32 + cc*8]);
        }
        constexpr int WC = BN/8;
#pragma unroll
        for (int c2=tid; c2 < 32*WC; c2 += 256){
            int r = c2/WC, cc = c2%WC;
            cp16(su32(&sW[r*WST + cc*8]),
                 &W[(size_t)(kt*32+r)*N + n0 + cc*8]);
        }
    };

    const int KT = K/32;
#pragma unroll
    for (int p=0; p<STAGES-1; p++){ stage(p, p); cp_commit(); }

    for (int kt = 0; kt < KT; kt++){
        if (kt+STAGES-1 < KT) stage(kt+STAGES-1, (kt+STAGES-1)%STAGES);
        cp_commit();
        cp_wait<STAGES-1>();
        __syncthreads();
        const __half* cA = sAbase + (kt%STAGES)*ASZ;
        const __half* cW = sWbase + (kt%STAGES)*WSZ;
#pragma unroll
        for (int ks=0; ks<2; ks++){
            unsigned a[2][4];
#pragma unroll
            for (int mt=0; mt<2; mt++){
                int row = wm*32 + mt*16 + (lane&7) + ((lane>>3)&1)*8;
                int col = ks*16 + (lane>>4)*8;
                ldm4(a[mt][0],a[mt][1],a[mt][2],a[mt][3], su32(&cA[row*AST+col]));
            }
            unsigned bfr[NG][4];
#pragma unroll
            for (int ng=0; ng<NG; ng++){
                int row = ks*16 + (lane&15);
                int col = wn*WN + ng*16 + (lane>>4)*8;
                ldm4t(bfr[ng][0],bfr[ng][1],bfr[ng][2],bfr[ng][3], su32(&cW[row*WST+col]));
            }
#pragma unroll
            for (int mt=0; mt<2; mt++)
#pragma unroll
                for (int ng=0; ng<NG; ng++){
                    mma_f16(acc[mt][ng*2],   a[mt][0],a[mt][1],a[mt][2],a[mt][3],
                            bfr[ng][0],bfr[ng][1]);
                    mma_f16(acc[mt][ng*2+1], a[mt][0],a[mt][1],a[mt][2],a[mt][3],
                            bfr[ng][2],bfr[ng][3]);
                }
        }
        __syncthreads();
    }

#pragma unroll
    for (int mt=0; mt<2; mt++){
        int row = m0 + wm*32 + mt*16;
#pragma unroll
        for (int nt=0; nt<NG*2; nt++){
            int col = n0 + wn*WN + nt*8 + 2*t;
            float b0 = bias[col]*bscale, b1 = bias[col+1]*bscale;
            st2(&C[(size_t)(row+g  )*CST + coff + col], acc[mt][nt][0]+b0, acc[mt][nt][1]+b1);
            st2(&C[(size_t)(row+g+8)*CST + coff + col], acc[mt][nt][2]+b0, acc[mt][nt][3]+b1);
        }
    }
}

// Fused Q-proj + K-proj + V-proj: flattened 384-CTA grid.
// bid < 256: Q-proj tile (n0 = (bid&7)*128, m0 = (bid>>3)*128)
// else: KV tile, z = (bid-256)>>6 selects key/value, m0 = ((bid-256)&63)*64
__global__ __launch_bounds__(256,2) void proj_fused(
    const float* __restrict__ bq, const float* __restrict__ bk,
    const float* __restrict__ bv)
{
    const int bid = blockIdx.x;
    if (bid < 256){
        gemm_core<128,128,3,__half>(h_query, h_Wq, bq, h_q,
            DMODEL, DMODEL, QSCALE, DMODEL, 0, (bid>>3)*128, (bid&7)*128);
    } else {
        const int r = bid - 256, z = r >> 6, by = r & 63;
        gemm_core<64,64,4,__half>(z ? h_value : h_key, z ? h_Wv : h_Wk,
            z ? bv : bk, h_kv, DK, DMODEL, 1.f, 2*DK, z*DK, by*64, 0);
    }
}

// O-projection (fp32 out)
__global__ __launch_bounds__(256,2) void oproj_k(
    const float* __restrict__ bo, float* __restrict__ C)
{
    gemm_core<128,128,3,float>(h_x, h_Wo, bo, C,
        DMODEL, DMODEL, 1.f, DMODEL, 0, (blockIdx.x>>3)*128, (blockIdx.x&7)*128);
}

#define GSM128 ((3*(128*40) + 3*(32*136))*2)    // 56832 (covers the KV path's 38912 too)

// ---------------------------------------------------------------------------
// fp16 flash attention (exact R11 kernel, best known: 244.2 us config).
// MQA flattened: CTA = 128 rows = 8 s x 16 heads; warp = one s (16 head-rows).
// Q pre-scaled by 0.125*log2(e) -> softmax via exp2 (f16x2 MUFU), online max,
// mask bias as mma C-init (exact), warp-voted rescale skip (exact),
// denominator l via ones-column mma. 2-stage static-smem cp.async pipeline.
// ---------------------------------------------------------------------------
__global__ __launch_bounds__(256,2) void flash_h(
    const __half* __restrict__ qp, const __half* __restrict__ kvp,
    const int* __restrict__ mask, __half* __restrict__ xo)
{
    constexpr int ST = 72;    // smem row stride halfs; cols 64-71 = [1,0,...,0]
    __shared__ __half sK[2][64*ST];
    __shared__ __half sV[2][64*ST];
    __shared__ int    sM[2][8*64];
    __half* sQ = &sK[0][0];   // 128*72 halfs == both sK buffers, prologue only

    const int tid = threadIdx.x, warp = tid>>5, lane = tid&31;
    const int g = lane>>2, t = lane&3;
    const int m0 = blockIdx.x*128;
    const int b  = m0 >> 15;
    const int s0 = (m0 & 32767) >> 4;
    const int sbase = b*SEQ;

    // ---- stage Q [128][64] via cp.async, extract A-fragments ----
    {
        int c = tid*4;
#pragma unroll
        for (int i=0;i<4;i++,c++){
            int r = c>>3, cc = c&7;
            cp16(su32(&sQ[r*ST + cc*8]),
                 &qp[(size_t)(sbase + s0 + (r>>4))*DMODEL + (r&15)*64 + cc*8]);
        }
        cp_commit(); cp_wait<0>();
        __syncthreads();
    }
    unsigned qa[4][4];
#pragma unroll
    for (int ks=0; ks<4; ks++){
        int row = warp*16 + (lane&7) + ((lane>>3)&1)*8;
        int col = ks*16 + (lane>>4)*8;
        ldm4(qa[ks][0],qa[ks][1],qa[ks][2],qa[ks][3], su32(&sQ[row*ST+col]));
    }
    __syncthreads();    // sQ region free -> K buffers

    // ---- init V ones-column region (cols 64-71) for both buffers ----
    if (tid < 128){
        int buf = tid >> 6, row = tid & 63;
        __half tmp[8] = {__float2half(1.f),__half(0),__half(0),__half(0),
                         __half(0),__half(0),__half(0),__half(0)};
        *(uint4*)&sV[buf][row*ST + 64] = *(uint4*)&tmp[0];
    }

    float o[8][4];
#pragma unroll
    for (int i=0;i<8;i++){ o[i][0]=0.f;o[i][1]=0.f;o[i][2]=0.f;o[i][3]=0.f; }
    float lacc[4] = {0.f,0.f,0.f,0.f};
    float mrow0=-1e30f, mrow1=-1e30f;

    auto stage = [&](int nk, int buf){
        int c = tid*2;
#pragma unroll
        for (int i=0;i<2;i++,c++){
            int r = c>>3, cc = c&7;
            const __half* kvrow = &kvp[(size_t)(sbase + nk + r)*(2*DK)];
            cp16(su32(&sK[buf][r*ST + cc*8]), kvrow + cc*8);
            cp16(su32(&sV[buf][r*ST + cc*8]), kvrow + DK + cc*8);
        }
        if (tid < 128){
            int r = tid>>4, cc = tid&15;
            cp16(su32(&sM[buf][r*64 + cc*4]),
                 &mask[((size_t)b*SEQ + s0 + r)*SEQ + nk + cc*4]);
        }
    };

    stage(0,0); cp_commit();

    for (int it = 0; it < SEQ/64; it++){
        if (it+1 < SEQ/64){ stage((it+1)*64, (it+1)&1); cp_commit(); cp_wait<1>(); }
        else              { cp_wait<0>(); }
        __syncthreads();
        const __half* cK = sK[it&1];
        const __half* cV = sV[it&1];
        const int*    cM = sM[it&1];

        // ---- S = Q K^T with mask bias as C-init (log2 domain) ----
        float sf[8][4];
#pragma unroll
        for (int jt=0; jt<8; jt++){
            unsigned kb[8];
            {
                int row = jt*8 + (lane&7);
                int col = (lane>>3)*8;
                ldm4(kb[0],kb[1],kb[2],kb[3], su32(&cK[row*ST + col]));
                ldm4(kb[4],kb[5],kb[6],kb[7], su32(&cK[row*ST + 32 + col]));
            }
            float mb0 = cM[warp*64 + jt*8 + 2*t    ] ? 0.f : -1e9f;
            float mb1 = cM[warp*64 + jt*8 + 2*t + 1] ? 0.f : -1e9f;
            sf[jt][0]=mb0; sf[jt][1]=mb1; sf[jt][2]=mb0; sf[jt][3]=mb1;
            mma_f16(sf[jt], qa[0][0],qa[0][1],qa[0][2],qa[0][3], kb[0],kb[1]);
            mma_f16(sf[jt], qa[1][0],qa[1][1],qa[1][2],qa[1][3], kb[2],kb[3]);
            mma_f16(sf[jt], qa[2][0],qa[2][1],qa[2][2],qa[2][3], kb[4],kb[5]);
            mma_f16(sf[jt], qa[3][0],qa[3][1],qa[3][2],qa[3][3], kb[6],kb[7]);
        }

        // ---- online softmax (base 2), P in f16 via h2exp2 ----
        float mx0=-1e30f, mx1=-1e30f;
#pragma unroll
        for (int jt=0; jt<8; jt++){
            mx0 = fmaxf(mx0, fmaxf(sf[jt][0], sf[jt][1]));
            mx1 = fmaxf(mx1, fmaxf(sf[jt][2], sf[jt][3]));
        }
        mx0 = fmaxf(mx0, __shfl_xor_sync(0xffffffffu, mx0, 1));
        mx0 = fmaxf(mx0, __shfl_xor_sync(0xffffffffu, mx0, 2));
        mx1 = fmaxf(mx1, __shfl_xor_sync(0xffffffffu, mx1, 1));
        mx1 = fmaxf(mx1, __shfl_xor_sync(0xffffffffu, mx1, 2));

        float mn0 = fmaxf(mrow0, mx0), mn1 = fmaxf(mrow1, mx1);
        // rescale only when some row max increased (skip is exact: sc==1.0)
        bool unchanged = (mn0 == mrow0) && (mn1 == mrow1);
        if (!__all_sync(0xffffffffu, unchanged)){
            float sc0 = ex2(mrow0 - mn0), sc1 = ex2(mrow1 - mn1);
#pragma unroll
            for (int nv=0; nv<8; nv++){
                o[nv][0]*=sc0; o[nv][1]*=sc0; o[nv][2]*=sc1; o[nv][3]*=sc1;
            }
            lacc[0]*=sc0; lacc[1]*=sc0; lacc[2]*=sc1; lacc[3]*=sc1;
        }
        mrow0 = mn0; mrow1 = mn1;

        unsigned pl[8], ph[8];
#pragma unroll
        for (int jt=0; jt<8; jt++){
            __half2 e0 = h2exp2(__floats2half2_rn(sf[jt][0]-mn0, sf[jt][1]-mn0));
            __half2 e1 = h2exp2(__floats2half2_rn(sf[jt][2]-mn1, sf[jt][3]-mn1));
            pl[jt] = *(unsigned*)&e0;
            ph[jt] = *(unsigned*)&e1;
        }

        // ---- O += P V ; l += P 1 (ones-column mma) ----
#pragma unroll
        for (int kt2=0; kt2<4; kt2++){
            unsigned a0 = pl[2*kt2],   a1 = ph[2*kt2];
            unsigned a2 = pl[2*kt2+1], a3 = ph[2*kt2+1];
#pragma unroll
            for (int dp=0; dp<4; dp++){
                unsigned r0,r1,r2,r3;
                int row = kt2*16 + (lane&15);
                int col = dp*16 + (lane>>4)*8;
                ldm4t(r0,r1,r2,r3, su32(&cV[row*ST + col]));
                mma_f16(o[dp*2],   a0,a1,a2,a3, r0,r1);
                mma_f16(o[dp*2+1], a0,a1,a2,a3, r2,r3);
            }
            unsigned l0r,l1r;
            ldm2t(l0r,l1r, su32(&cV[(kt2*16 + (lane&15))*ST + 64]));
            mma_f16(lacc, a0,a1,a2,a3, l0r,l1r);
        }
        __syncthreads();
    }

    // ---- broadcast l (col 64 lives in t=0 lanes, reg 0/2), normalize, write ----
    float lv0 = __shfl_sync(0xffffffffu, lacc[0], lane & 28);
    float lv1 = __shfl_sync(0xffffffffu, lacc[2], lane & 28);
    float inv0 = 1.f/lv0, inv1 = 1.f/lv1;
    __half* orow = &xo[(size_t)(sbase + s0 + warp)*DMODEL];
#pragma unroll
    for (int nt=0; nt<8; nt++){
        int col = nt*8 + 2*t;
        st2(&orow[g*64 + col],     o[nt][0]*inv0, o[nt][1]*inv0);
        st2(&orow[(g+8)*64 + col], o[nt][2]*inv1, o[nt][3]*inv1);
    }
}

// ---------------------------------------------------------------------------
extern "C" void kernel_launch(void* const* d_in, const int* in_sizes, int n_in,
                              void* d_out, int out_size)
{
    const float* query = (const float*)d_in[0];
    const float* key   = (const float*)d_in[1];
    const float* value = (const float*)d_in[2];
    const int*   mask  = (const int*)  d_in[3];
    const float* Wq = (const float*)d_in[4];
    const float* bq = (const float*)d_in[5];
    const float* Wk = (const float*)d_in[6];
    const float* bk = (const float*)d_in[7];
    const float* Wv = (const float*)d_in[8];
    const float* bv = (const float*)d_in[9];
    const float* Wo = (const float*)d_in[10];
    const float* bo = (const float*)d_in[11];
    float* out = (float*)d_out;

    __half *gq,*gkv,*gx;
    cudaGetSymbolAddress((void**)&gq,  h_q);
    cudaGetSymbolAddress((void**)&gkv, h_kv);
    cudaGetSymbolAddress((void**)&gx,  h_x);

    cudaFuncSetAttribute(proj_fused, cudaFuncAttributeMaxDynamicSharedMemorySize, GSM128);
    cudaFuncSetAttribute(oproj_k,    cudaFuncAttributeMaxDynamicSharedMemorySize, GSM128);

    // all converts in one launch
    conv_all<<<7232, 256>>>(query, key, value, Wq, Wo, Wk, Wv);

    // Q + K + V projections fused into one launch (384 CTAs)
    proj_fused<<<384, 256, GSM128>>>(bq, bk, bv);

    // fused MQA flash attention
    flash_h<<<(NB*SEQ*NH)/128, 256>>>(gq, gkv, mask, gx);

    // output projection (fp32 out)
    oproj_k<<<256, 256, GSM128>>>(bo, out);
}

// round 17
// speedup vs baseline: 1.0708x; 1.0178x over previous
#include <cuda_runtime.h>
#include <cuda_fp16.h>
#include <cstdint>

#define SEQ 2048
#define DMODEL 1024
#define NH 16
#define DK 64
#define NB 2
#define ROWS (NB*SEQ)

// 0.125 * log2(e): folds the 1/sqrt(dk) scale and the exp->exp2 change
#define QSCALE 0.18033688f

// ---------------- scratch (device globals: allocation-free) ----------------
__device__ __half h_query[ROWS*DMODEL];
__device__ __half h_key  [ROWS*DMODEL];
__device__ __half h_value[ROWS*DMODEL];
__device__ __half h_Wq[DMODEL*DMODEL];
__device__ __half h_Wo[DMODEL*DMODEL];
__device__ __half h_Wk[DMODEL*DK];
__device__ __half h_Wv[DMODEL*DK];
__device__ __half h_q [ROWS*DMODEL];
__device__ __half h_kv[ROWS*2*DK];        // packed [4096][128]: cols 0-63 K, 64-127 V
__device__ __half h_x [ROWS*DMODEL];

// ---------------- ptx helpers ----------------
__device__ __forceinline__ unsigned su32(const void* p){
    return (unsigned)__cvta_generic_to_shared(p);
}
__device__ __forceinline__ void cp16(unsigned s, const void* g){
    asm volatile("cp.async.ca.shared.global [%0], [%1], 16;" :: "r"(s), "l"(g));
}
__device__ __forceinline__ void cp_commit(){ asm volatile("cp.async.commit_group;"); }
template<int N> __device__ __forceinline__ void cp_wait(){
    asm volatile("cp.async.wait_group %0;" :: "n"(N));
}
__device__ __forceinline__ void ldm4(unsigned& r0,unsigned& r1,unsigned& r2,unsigned& r3,unsigned a){
    asm volatile("ldmatrix.sync.aligned.m8n8.x4.shared.b16 {%0,%1,%2,%3}, [%4];"
        : "=r"(r0),"=r"(r1),"=r"(r2),"=r"(r3) : "r"(a));
}
__device__ __forceinline__ void ldm4t(unsigned& r0,unsigned& r1,unsigned& r2,unsigned& r3,unsigned a){
    asm volatile("ldmatrix.sync.aligned.m8n8.x4.trans.shared.b16 {%0,%1,%2,%3}, [%4];"
        : "=r"(r0),"=r"(r1),"=r"(r2),"=r"(r3) : "r"(a));
}
__device__ __forceinline__ void ldm2t(unsigned& r0,unsigned& r1,unsigned a){
    asm volatile("ldmatrix.sync.aligned.m8n8.x2.trans.shared.b16 {%0,%1}, [%2];"
        : "=r"(r0),"=r"(r1) : "r"(a));
}
__device__ __forceinline__ void mma_f16(float* c, unsigned a0,unsigned a1,unsigned a2,unsigned a3,
                                        unsigned b0, unsigned b1){
    asm volatile("mma.sync.aligned.m16n8k16.row.col.f32.f16.f16.f32 "
        "{%0,%1,%2,%3},{%4,%5,%6,%7},{%8,%9},{%0,%1,%2,%3};"
        : "+f"(c[0]),"+f"(c[1]),"+f"(c[2]),"+f"(c[3])
        : "r"(a0),"r"(a1),"r"(a2),"r"(a3),"r"(b0),"r"(b1));
}
__device__ __forceinline__ float ex2(float x){
    float r; asm("ex2.approx.f32 %0, %1;" : "=f"(r) : "f"(x)); return r;
}
__device__ __forceinline__ void st2(__half* p, float x, float y){
    *(__half2*)p = __floats2half2_rn(x, y);
}
__device__ __forceinline__ void st2(float* p, float x, float y){
    *(float2*)p = make_float2(x, y);
}

// ---------------- all fp32 -> fp16 converts in ONE launch ----------------
__global__ void conv_all(const float* __restrict__ q, const float* __restrict__ k,
                         const float* __restrict__ v, const float* __restrict__ Wq,
                         const float* __restrict__ Wo, const float* __restrict__ Wk,
                         const float* __restrict__ Wv){
    int bid = blockIdx.x;
    const float* s; __half* d; float sc = 1.f; int base;
    if      (bid < 2048){ s=q;  d=h_query; base=bid; }
    else if (bid < 4096){ s=k;  d=h_key;   base=bid-2048; }
    else if (bid < 6144){ s=v;  d=h_value; base=bid-4096; }
    else if (bid < 6656){ s=Wq; d=h_Wq;    base=bid-6144; sc=QSCALE; }
    else if (bid < 7168){ s=Wo; d=h_Wo;    base=bid-6656; }
    else if (bid < 7200){ s=Wk; d=h_Wk;    base=bid-7168; }
    else                { s=Wv; d=h_Wv;    base=bid-7200; }
    int i = (base*256 + threadIdx.x)*8;
    float4 a = *(const float4*)&s[i];
    float4 b2 = *(const float4*)&s[i+4];
    *(__half2*)&d[i]   = __floats2half2_rn(a.x*sc, a.y*sc);
    *(__half2*)&d[i+2] = __floats2half2_rn(a.z*sc, a.w*sc);
    *(__half2*)&d[i+4] = __floats2half2_rn(b2.x*sc, b2.y*sc);
    *(__half2*)&d[i+6] = __floats2half2_rn(b2.z*sc, b2.w*sc);
}

// ---------------------------------------------------------------------------
// fp16 GEMM core: C tile [BM x BN] at (m0, n0) = A[M,K] @ W[K,N] + bias*bscale.
// BK template (32 or 64), STAGES-deep cp.async pipeline, dynamic smem.
// 256 threads, 8 warps (BM/32 m) x (8/(BM/32) n).
// ---------------------------------------------------------------------------
template<int BM, int BN, int BK, int STAGES, typename OUT>
__device__ __forceinline__ void gemm_core(
    const __half* __restrict__ A, const __half* __restrict__ W,
    const float* __restrict__ bias, OUT* __restrict__ C,
    int N, int K, float bscale, int CST, int coff, int m0, int n0)
{
    constexpr int AST = BK + 8;
    constexpr int WST = BN + 8;
    constexpr int ASZ = BM*AST;
    constexpr int WSZ = BK*WST;
    constexpr int MW  = BM/32;
    constexpr int NW  = 8/MW;
    constexpr int WN  = BN/NW;
    constexpr int NG  = WN/16;
    constexpr int KS  = BK/16;

    extern __shared__ __half gsm[];
    __half* sAbase = gsm;
    __half* sWbase = gsm + STAGES*ASZ;

    const int tid = threadIdx.x, warp = tid>>5, lane = tid&31;
    const int wm = warp % MW, wn = warp / MW;
    const int g = lane>>2, t = lane&3;

    float acc[2][NG*2][4];
#pragma unroll
    for (int a=0;a<2;a++)
#pragma unroll
        for (int b=0;b<NG*2;b++)
#pragma unroll
            for (int c=0;c<4;c++) acc[a][b][c]=0.f;

    auto stage = [&](int kt, int buf){
        __half* sA = sAbase + buf*ASZ;
        __half* sW = sWbase + buf*WSZ;
        constexpr int AC = BK/8;
#pragma unroll
        for (int c = tid; c < BM*AC; c += 256){
            int r = c/AC, cc = c%AC;
            cp16(su32(&sA[r*AST + cc*8]),
                 &A[(size_t)(m0+r)*K + kt*BK + cc*8]);
        }
        constexpr int WC = BN/8;
#pragma unroll
        for (int c2=tid; c2 < BK*WC; c2 += 256){
            int r = c2/WC, cc = c2%WC;
            cp16(su32(&sW[r*WST + cc*8]),
                 &W[(size_t)(kt*BK+r)*N + n0 + cc*8]);
        }
    };

    const int KT = K/BK;
#pragma unroll
    for (int p=0; p<STAGES-1; p++){ stage(p, p); cp_commit(); }

    for (int kt = 0; kt < KT; kt++){
        if (kt+STAGES-1 < KT) stage(kt+STAGES-1, (kt+STAGES-1)%STAGES);
        cp_commit();                       // empty group in tail keeps counts uniform
        cp_wait<STAGES-1>();
        __syncthreads();
        const __half* cA = sAbase + (kt%STAGES)*ASZ;
        const __half* cW = sWbase + (kt%STAGES)*WSZ;
#pragma unroll
        for (int ks=0; ks<KS; ks++){
            unsigned a[2][4];
#pragma unroll
            for (int mt=0; mt<2; mt++){
                int row = wm*32 + mt*16 + (lane&7) + ((lane>>3)&1)*8;
                int col = ks*16 + (lane>>4)*8;
                ldm4(a[mt][0],a[mt][1],a[mt][2],a[mt][3], su32(&cA[row*AST+col]));
            }
            unsigned bfr[NG][4];
#pragma unroll
            for (int ng=0; ng<NG; ng++){
                int row = ks*16 + (lane&15);
                int col = wn*WN + ng*16 + (lane>>4)*8;
                ldm4t(bfr[ng][0],bfr[ng][1],bfr[ng][2],bfr[ng][3], su32(&cW[row*WST+col]));
            }
#pragma unroll
            for (int mt=0; mt<2; mt++)
#pragma unroll
                for (int ng=0; ng<NG; ng++){
                    mma_f16(acc[mt][ng*2],   a[mt][0],a[mt][1],a[mt][2],a[mt][3],
                            bfr[ng][0],bfr[ng][1]);
                    mma_f16(acc[mt][ng*2+1], a[mt][0],a[mt][1],a[mt][2],a[mt][3],
                            bfr[ng][2],bfr[ng][3]);
                }
        }
        __syncthreads();
    }

#pragma unroll
    for (int mt=0; mt<2; mt++){
        int row = m0 + wm*32 + mt*16;
#pragma unroll
        for (int nt=0; nt<NG*2; nt++){
            int col = n0 + wn*WN + nt*8 + 2*t;
            float b0 = bias[col]*bscale, b1 = bias[col+1]*bscale;
            st2(&C[(size_t)(row+g  )*CST + coff + col], acc[mt][nt][0]+b0, acc[mt][nt][1]+b1);
            st2(&C[(size_t)(row+g+8)*CST + coff + col], acc[mt][nt][2]+b0, acc[mt][nt][3]+b1);
        }
    }
}

// Fused Q-proj (BK=64, 2-stage) + K/V-proj (BK=32, 4-stage): 384-CTA grid.
__global__ __launch_bounds__(256,2) void proj_fused(
    const float* __restrict__ bq, const float* __restrict__ bk,
    const float* __restrict__ bv)
{
    const int bid = blockIdx.x;
    if (bid < 256){
        gemm_core<128,128,64,2,__half>(h_query, h_Wq, bq, h_q,
            DMODEL, DMODEL, QSCALE, DMODEL, 0, (bid>>3)*128, (bid&7)*128);
    } else {
        const int r = bid - 256, z = r >> 6, by = r & 63;
        gemm_core<64,64,32,4,__half>(z ? h_value : h_key, z ? h_Wv : h_Wk,
            z ? bv : bk, h_kv, DK, DMODEL, 1.f, 2*DK, z*DK, by*64, 0);
    }
}

// O-projection (fp32 out, BK=64, 2-stage)
__global__ __launch_bounds__(256,2) void oproj_k(
    const float* __restrict__ bo, float* __restrict__ C)
{
    gemm_core<128,128,64,2,float>(h_x, h_Wo, bo, C,
        DMODEL, DMODEL, 1.f, DMODEL, 0, (blockIdx.x>>3)*128, (blockIdx.x&7)*128);
}

// smem: BK=64 2-stage: 2*(128*72 + 64*136) halfs = 71680 B (covers KV's 38912)
#define GSMQ ((2*(128*72) + 2*(64*136))*2)   // 71680

// ---------------------------------------------------------------------------
// fp16 flash attention (exact R11/R15 kernel — best known).
// ---------------------------------------------------------------------------
__global__ __launch_bounds__(256,2) void flash_h(
    const __half* __restrict__ qp, const __half* __restrict__ kvp,
    const int* __restrict__ mask, __half* __restrict__ xo)
{
    constexpr int ST = 72;    // smem row stride halfs; cols 64-71 = [1,0,...,0]
    __shared__ __half sK[2][64*ST];
    __shared__ __half sV[2][64*ST];
    __shared__ int    sM[2][8*64];
    __half* sQ = &sK[0][0];

    const int tid = threadIdx.x, warp = tid>>5, lane = tid&31;
    const int g = lane>>2, t = lane&3;
    const int m0 = blockIdx.x*128;
    const int b  = m0 >> 15;
    const int s0 = (m0 & 32767) >> 4;
    const int sbase = b*SEQ;

    {
        int c = tid*4;
#pragma unroll
        for (int i=0;i<4;i++,c++){
            int r = c>>3, cc = c&7;
            cp16(su32(&sQ[r*ST + cc*8]),
                 &qp[(size_t)(sbase + s0 + (r>>4))*DMODEL + (r&15)*64 + cc*8]);
        }
        cp_commit(); cp_wait<0>();
        __syncthreads();
    }
    unsigned qa[4][4];
#pragma unroll
    for (int ks=0; ks<4; ks++){
        int row = warp*16 + (lane&7) + ((lane>>3)&1)*8;
        int col = ks*16 + (lane>>4)*8;
        ldm4(qa[ks][0],qa[ks][1],qa[ks][2],qa[ks][3], su32(&sQ[row*ST+col]));
    }
    __syncthreads();

    if (tid < 128){
        int buf = tid >> 6, row = tid & 63;
        __half tmp[8] = {__float2half(1.f),__half(0),__half(0),__half(0),
                         __half(0),__half(0),__half(0),__half(0)};
        *(uint4*)&sV[buf][row*ST + 64] = *(uint4*)&tmp[0];
    }

    float o[8][4];
#pragma unroll
    for (int i=0;i<8;i++){ o[i][0]=0.f;o[i][1]=0.f;o[i][2]=0.f;o[i][3]=0.f; }
    float lacc[4] = {0.f,0.f,0.f,0.f};
    float mrow0=-1e30f, mrow1=-1e30f;

    auto stage = [&](int nk, int buf){
        int c = tid*2;
#pragma unroll
        for (int i=0;i<2;i++,c++){
            int r = c>>3, cc = c&7;
            const __half* kvrow = &kvp[(size_t)(sbase + nk + r)*(2*DK)];
            cp16(su32(&sK[buf][r*ST + cc*8]), kvrow + cc*8);
            cp16(su32(&sV[buf][r*ST + cc*8]), kvrow + DK + cc*8);
        }
        if (tid < 128){
            int r = tid>>4, cc = tid&15;
            cp16(su32(&sM[buf][r*64 + cc*4]),
                 &mask[((size_t)b*SEQ + s0 + r)*SEQ + nk + cc*4]);
        }
    };

    stage(0,0); cp_commit();

    for (int it = 0; it < SEQ/64; it++){
        if (it+1 < SEQ/64){ stage((it+1)*64, (it+1)&1); cp_commit(); cp_wait<1>(); }
        else              { cp_wait<0>(); }
        __syncthreads();
        const __half* cK = sK[it&1];
        const __half* cV = sV[it&1];
        const int*    cM = sM[it&1];

        float sf[8][4];
#pragma unroll
        for (int jt=0; jt<8; jt++){
            unsigned kb[8];
            {
                int row = jt*8 + (lane&7);
                int col = (lane>>3)*8;
                ldm4(kb[0],kb[1],kb[2],kb[3], su32(&cK[row*ST + col]));
                ldm4(kb[4],kb[5],kb[6],kb[7], su32(&cK[row*ST + 32 + col]));
            }
            float mb0 = cM[warp*64 + jt*8 + 2*t    ] ? 0.f : -1e9f;
            float mb1 = cM[warp*64 + jt*8 + 2*t + 1] ? 0.f : -1e9f;
            sf[jt][0]=mb0; sf[jt][1]=mb1; sf[jt][2]=mb0; sf[jt][3]=mb1;
            mma_f16(sf[jt], qa[0][0],qa[0][1],qa[0][2],qa[0][3], kb[0],kb[1]);
            mma_f16(sf[jt], qa[1][0],qa[1][1],qa[1][2],qa[1][3], kb[2],kb[3]);
            mma_f16(sf[jt], qa[2][0],qa[2][1],qa[2][2],qa[2][3], kb[4],kb[5]);
            mma_f16(sf[jt], qa[3][0],qa[3][1],qa[3][2],qa[3][3], kb[6],kb[7]);
        }

        float mx0=-1e30f, mx1=-1e30f;
#pragma unroll
        for (int jt=0; jt<8; jt++){
            mx0 = fmaxf(mx0, fmaxf(sf[jt][0], sf[jt][1]));
            mx1 = fmaxf(mx1, fmaxf(sf[jt][2], sf[jt][3]));
        }
        mx0 = fmaxf(mx0, __shfl_xor_sync(0xffffffffu, mx0, 1));
        mx0 = fmaxf(mx0, __shfl_xor_sync(0xffffffffu, mx0, 2));
        mx1 = fmaxf(mx1, __shfl_xor_sync(0xffffffffu, mx1, 1));
        mx1 = fmaxf(mx1, __shfl_xor_sync(0xffffffffu, mx1, 2));

        float mn0 = fmaxf(mrow0, mx0), mn1 = fmaxf(mrow1, mx1);
        bool unchanged = (mn0 == mrow0) && (mn1 == mrow1);
        if (!__all_sync(0xffffffffu, unchanged)){
            float sc0 = ex2(mrow0 - mn0), sc1 = ex2(mrow1 - mn1);
#pragma unroll
            for (int nv=0; nv<8; nv++){
                o[nv][0]*=sc0; o[nv][1]*=sc0; o[nv][2]*=sc1; o[nv][3]*=sc1;
            }
            lacc[0]*=sc0; lacc[1]*=sc0; lacc[2]*=sc1; lacc[3]*=sc1;
        }
        mrow0 = mn0; mrow1 = mn1;

        unsigned pl[8], ph[8];
#pragma unroll
        for (int jt=0; jt<8; jt++){
            __half2 e0 = h2exp2(__floats2half2_rn(sf[jt][0]-mn0, sf[jt][1]-mn0));
            __half2 e1 = h2exp2(__floats2half2_rn(sf[jt][2]-mn1, sf[jt][3]-mn1));
            pl[jt] = *(unsigned*)&e0;
            ph[jt] = *(unsigned*)&e1;
        }

#pragma unroll
        for (int kt2=0; kt2<4; kt2++){
            unsigned a0 = pl[2*kt2],   a1 = ph[2*kt2];
            unsigned a2 = pl[2*kt2+1], a3 = ph[2*kt2+1];
#pragma unroll
            for (int dp=0; dp<4; dp++){
                unsigned r0,r1,r2,r3;
                int row = kt2*16 + (lane&15);
                int col = dp*16 + (lane>>4)*8;
                ldm4t(r0,r1,r2,r3, su32(&cV[row*ST + col]));
                mma_f16(o[dp*2],   a0,a1,a2,a3, r0,r1);
                mma_f16(o[dp*2+1], a0,a1,a2,a3, r2,r3);
            }
            unsigned l0r,l1r;
            ldm2t(l0r,l1r, su32(&cV[(kt2*16 + (lane&15))*ST + 64]));
            mma_f16(lacc, a0,a1,a2,a3, l0r,l1r);
        }
        __syncthreads();
    }

    float lv0 = __shfl_sync(0xffffffffu, lacc[0], lane & 28);
    float lv1 = __shfl_sync(0xffffffffu, lacc[2], lane & 28);
    float inv0 = 1.f/lv0, inv1 = 1.f/lv1;
    __half* orow = &xo[(size_t)(sbase + s0 + warp)*DMODEL];
#pragma unroll
    for (int nt=0; nt<8; nt++){
        int col = nt*8 + 2*t;
        st2(&orow[g*64 + col],     o[nt][0]*inv0, o[nt][1]*inv0);
        st2(&orow[(g+8)*64 + col], o[nt][2]*inv1, o[nt][3]*inv1);
    }
}

// ---------------------------------------------------------------------------
extern "C" void kernel_launch(void* const* d_in, const int* in_sizes, int n_in,
                              void* d_out, int out_size)
{
    const float* query = (const float*)d_in[0];
    const float* key   = (const float*)d_in[1];
    const float* value = (const float*)d_in[2];
    const int*   mask  = (const int*)  d_in[3];
    const float* Wq = (const float*)d_in[4];
    const float* bq = (const float*)d_in[5];
    const float* Wk = (const float*)d_in[6];
    const float* bk = (const float*)d_in[7];
    const float* Wv = (const float*)d_in[8];
    const float* bv = (const float*)d_in[9];
    const float* Wo = (const float*)d_in[10];
    const float* bo = (const float*)d_in[11];
    float* out = (float*)d_out;

    __half *gq,*gkv,*gx;
    cudaGetSymbolAddress((void**)&gq,  h_q);
    cudaGetSymbolAddress((void**)&gkv, h_kv);
    cudaGetSymbolAddress((void**)&gx,  h_x);

    cudaFuncSetAttribute(proj_fused, cudaFuncAttributeMaxDynamicSharedMemorySize, GSMQ);
    cudaFuncSetAttribute(oproj_k,    cudaFuncAttributeMaxDynamicSharedMemorySize, GSMQ);

    // all converts in one launch
    conv_all<<<7232, 256>>>(query, key, value, Wq, Wo, Wk, Wv);

    // Q + K + V projections fused into one launch (384 CTAs)
    proj_fused<<<384, 256, GSMQ>>>(bq, bk, bv);

    // fused MQA flash attention
    flash_h<<<(NB*SEQ*NH)/128, 256>>>(gq, gkv, mask, gx);

    // output projection (fp32 out)
    oproj_k<<<256, 256, GSMQ>>>(bo, out);
}